// round 11
// baseline (speedup 1.0000x reference)
#include <cuda_runtime.h>
#include <cuda_fp16.h>
#include <math.h>

// Problem constants
#define Bsz 8
#define Sq  2048
#define Dm  256
#define Hh  4
#define Dk  64
#define NTOK (Bsz*Sq)          // 16384
#define OUT0_ELEMS ((size_t)NTOK*Dm) // 4194304
#define NROWS (Bsz*Hh*Sq)      // 65536 (b,h,q) rows
#define NXT 16                 // k-tiles per score row (2048/128)

// ---------------- scratch (static device globals; allocation-free contract) ---
__device__ __half g_Q[(size_t)Bsz*Hh*Sq*Dk];   // (b,h,q,d) fp16, 8MB
__device__ __half g_K[(size_t)Bsz*Hh*Sq*Dk];   // 8MB
__device__ __half g_Vt[(size_t)Bsz*Dm*Sq];     // V^T (b,d,tok) fp16, 8MB
__device__ __half g_E[(size_t)Bsz*Hh*Sq*Sq];   // exp(scores) fp16, 256MiB
__device__ float  g_O[(size_t)NTOK*Dm];        // attn output pre-proj, 16MB
__device__ float  g_Zp[(size_t)NXT*NROWS];     // per-k-tile row-sum partials (fp32)
__device__ float  g_RZ[(size_t)NROWS];         // 0.25 / rowsum

// =============================================================================
// helpers
// =============================================================================
__device__ __forceinline__ unsigned f2tf(float f) {
    unsigned u;
    asm("cvt.rna.tf32.f32 %0, %1;" : "=r"(u) : "f"(f));
    return u;
}
__device__ __forceinline__ void mma_tf32(float c[4],
    unsigned a0, unsigned a1, unsigned a2, unsigned a3,
    unsigned b0, unsigned b1)
{
    asm volatile(
        "mma.sync.aligned.m16n8k8.row.col.f32.tf32.tf32.f32 "
        "{%0,%1,%2,%3},{%4,%5,%6,%7},{%8,%9},{%0,%1,%2,%3};"
        : "+f"(c[0]), "+f"(c[1]), "+f"(c[2]), "+f"(c[3])
        : "r"(a0), "r"(a1), "r"(a2), "r"(a3), "r"(b0), "r"(b1));
}
// m16n8k16 fp16 MMA, fp32 accumulate
__device__ __forceinline__ void mma_f16(float c[4],
    unsigned a0, unsigned a1, unsigned a2, unsigned a3,
    unsigned b0, unsigned b1)
{
    asm volatile(
        "mma.sync.aligned.m16n8k16.row.col.f32.f16.f16.f32 "
        "{%0,%1,%2,%3},{%4,%5,%6,%7},{%8,%9},{%0,%1,%2,%3};"
        : "+f"(c[0]), "+f"(c[1]), "+f"(c[2]), "+f"(c[3])
        : "r"(a0), "r"(a1), "r"(a2), "r"(a3), "r"(b0), "r"(b1));
}
__device__ __forceinline__ void cp_async16(void* smem, const void* gmem) {
    unsigned saddr = (unsigned)__cvta_generic_to_shared(smem);
    asm volatile("cp.async.cg.shared.global [%0], [%1], 16;\n"
                 :: "r"(saddr), "l"(gmem));
}
__device__ __forceinline__ void cp_commit() {
    asm volatile("cp.async.commit_group;\n");
}
template<int N>
__device__ __forceinline__ void cp_wait() {
    asm volatile("cp.async.wait_group %0;\n" :: "n"(N));
}
__device__ __forceinline__ void stg_cs16(float* p, float4 v) {
    asm volatile("st.global.cs.v4.f32 [%0], {%1,%2,%3,%4};"
                 :: "l"(p), "f"(v.x), "f"(v.y), "f"(v.z), "f"(v.w) : "memory");
}
__device__ __forceinline__ void stg_cs4(unsigned* p, unsigned v) {
    asm volatile("st.global.cs.b32 [%0], %1;" :: "l"(p), "r"(v) : "memory");
}
__device__ __forceinline__ uint4 ldg_cs16(const void* p) {
    uint4 v;
    asm volatile("ld.global.cs.v4.b32 {%0,%1,%2,%3}, [%4];"
                 : "=r"(v.x), "=r"(v.y), "=r"(v.z), "=r"(v.w) : "l"(p));
    return v;
}

#define STAGES 4

// =============================================================================
// Fused QKV projection (tf32 GEMM, fp16 outputs): grid.z selects operands.
// z=0/1: Q/K head-major fp16 scatter. z=2: V^T fp16 (b, d, tok).
// =============================================================================
__global__ void __launch_bounds__(128, 2) qkv_proj_kernel(
    const float* __restrict__ q, const float* __restrict__ k, const float* __restrict__ v,
    const float* __restrict__ Wq, const float* __restrict__ Wk, const float* __restrict__ Wv,
    const float* __restrict__ bq, const float* __restrict__ bk, const float* __restrict__ bv,
    __half* __restrict__ Cq, __half* __restrict__ Ck, __half* __restrict__ Vt)
{
    extern __shared__ float dsm[];
    float (*As)[128][20]  = (float(*)[128][20])dsm;
    float (*Bs)[16][136]  = (float(*)[16][136])(dsm + STAGES * 128 * 20);

    const int sel = blockIdx.z;
    const float* A    = sel == 0 ? q  : sel == 1 ? k  : v;
    const float* B    = sel == 0 ? Wq : sel == 1 ? Wk : Wv;
    const float* bias = sel == 0 ? bq : sel == 1 ? bk : bv;

    const int tid  = threadIdx.x;
    const int lane = tid & 31;
    const int wid  = tid >> 5;
    const int g = lane >> 2, t = lane & 3;
    const int m0 = (wid & 1) * 64;
    const int n0 = (wid >> 1) * 64;

    const float* Ab = A + (size_t)blockIdx.y * 128 * Dm;
    const float* Bb = B + blockIdx.x * 128;

    const int arow = tid >> 2;
    const int acol = (tid & 3) * 4;
    const int brow = tid >> 5;
    const int bcol = (tid & 31) * 4;

    const int NKT = Dm / 16;   // 16

    auto issue = [&](int kt, int st) {
#pragma unroll
        for (int i = 0; i < 4; i++)
            cp_async16(&As[st][arow + 32 * i][acol],
                       Ab + (size_t)(arow + 32 * i) * Dm + kt * 16 + acol);
#pragma unroll
        for (int i = 0; i < 4; i++)
            cp_async16(&Bs[st][brow + 4 * i][bcol],
                       Bb + (size_t)(kt * 16 + brow + 4 * i) * Dm + bcol);
        cp_commit();
    };

#pragma unroll
    for (int s = 0; s < STAGES - 1; ++s) issue(s, s);

    float acc[4][8][4];
#pragma unroll
    for (int mi = 0; mi < 4; mi++)
#pragma unroll
        for (int ni = 0; ni < 8; ni++)
#pragma unroll
            for (int r = 0; r < 4; r++) acc[mi][ni][r] = 0.f;

    for (int kt = 0; kt < NKT; ++kt) {
        cp_wait<STAGES - 2>();
        __syncthreads();
        const int buf = kt % STAGES;
        if (kt + STAGES - 1 < NKT) issue(kt + STAGES - 1, (kt + STAGES - 1) % STAGES);
        else cp_commit();

#pragma unroll
        for (int ks = 0; ks < 2; ++ks) {
            const int kb = ks * 8;
            unsigned a[4][4], b[8][2];
#pragma unroll
            for (int mi = 0; mi < 4; mi++) {
                int r = m0 + mi * 16 + g;
                a[mi][0] = f2tf(As[buf][r][kb + t]);
                a[mi][1] = f2tf(As[buf][r + 8][kb + t]);
                a[mi][2] = f2tf(As[buf][r][kb + 4 + t]);
                a[mi][3] = f2tf(As[buf][r + 8][kb + 4 + t]);
            }
#pragma unroll
            for (int ni = 0; ni < 8; ni++) {
                int cn = n0 + ni * 8 + g;
                b[ni][0] = f2tf(Bs[buf][kb + t][cn]);
                b[ni][1] = f2tf(Bs[buf][kb + 4 + t][cn]);
            }
#pragma unroll
            for (int mi = 0; mi < 4; mi++)
#pragma unroll
                for (int ni = 0; ni < 8; ni++)
                    mma_tf32(acc[mi][ni], a[mi][0], a[mi][1], a[mi][2], a[mi][3],
                             b[ni][0], b[ni][1]);
        }
        __syncthreads();
    }

    const int rbase = blockIdx.y * 128 + m0;
    const int cbase = blockIdx.x * 128 + n0;
#pragma unroll
    for (int mi = 0; mi < 4; mi++) {
#pragma unroll
        for (int ni = 0; ni < 8; ni++) {
            int r = rbase + mi * 16 + g;
            int c = cbase + ni * 8 + 2 * t;
            float2 bb = *(const float2*)&bias[c];
            float2 v0 = { acc[mi][ni][0] + bb.x, acc[mi][ni][1] + bb.y };
            float2 v1 = { acc[mi][ni][2] + bb.x, acc[mi][ni][3] + bb.y };
            if (sel < 2) {
                __half* C = sel == 0 ? Cq : Ck;
                int b0i = r >> 11, q0 = r & 2047;
                int h = c >> 6, d = c & 63;
                __half2 h0 = __floats2half2_rn(v0.x, v0.y);
                __half2 h1 = __floats2half2_rn(v1.x, v1.y);
                *(__half2*)&C[((size_t)((b0i * Hh + h) * Sq) + q0) * Dk + d] = h0;
                int r1 = r + 8;
                int b1i = r1 >> 11, q1 = r1 & 2047;
                *(__half2*)&C[((size_t)((b1i * Hh + h) * Sq) + q1) * Dk + d] = h1;
            } else {
                int b0i = r >> 11, tok0 = r & 2047;
                Vt[((size_t)(b0i * Dm + c)     * Sq) + tok0] = __float2half_rn(v0.x);
                Vt[((size_t)(b0i * Dm + c + 1) * Sq) + tok0] = __float2half_rn(v0.y);
                int r1 = r + 8;
                int b1i = r1 >> 11, tok1 = r1 & 2047;
                Vt[((size_t)(b1i * Dm + c)     * Sq) + tok1] = __float2half_rn(v1.x);
                Vt[((size_t)(b1i * Dm + c + 1) * Sq) + tok1] = __float2half_rn(v1.y);
            }
        }
    }
}

// =============================================================================
// Final projection: out = Opre @ W_o + b_o (tf32, fp32 in/out)
// =============================================================================
__global__ void __launch_bounds__(128, 2) oproj_kernel(
    const float* __restrict__ A, const float* __restrict__ B,
    float* __restrict__ C, const float* __restrict__ bias)
{
    extern __shared__ float dsm[];
    float (*As)[128][20]  = (float(*)[128][20])dsm;
    float (*Bs)[16][136]  = (float(*)[16][136])(dsm + STAGES * 128 * 20);

    const int tid  = threadIdx.x;
    const int lane = tid & 31;
    const int wid  = tid >> 5;
    const int g = lane >> 2, t = lane & 3;
    const int m0 = (wid & 1) * 64;
    const int n0 = (wid >> 1) * 64;

    const float* Ab = A + (size_t)blockIdx.y * 128 * Dm;
    const float* Bb = B + blockIdx.x * 128;

    const int arow = tid >> 2;
    const int acol = (tid & 3) * 4;
    const int brow = tid >> 5;
    const int bcol = (tid & 31) * 4;

    const int NKT = Dm / 16;

    auto issue = [&](int kt, int st) {
#pragma unroll
        for (int i = 0; i < 4; i++)
            cp_async16(&As[st][arow + 32 * i][acol],
                       Ab + (size_t)(arow + 32 * i) * Dm + kt * 16 + acol);
#pragma unroll
        for (int i = 0; i < 4; i++)
            cp_async16(&Bs[st][brow + 4 * i][bcol],
                       Bb + (size_t)(kt * 16 + brow + 4 * i) * Dm + bcol);
        cp_commit();
    };

#pragma unroll
    for (int s = 0; s < STAGES - 1; ++s) issue(s, s);

    float acc[4][8][4];
#pragma unroll
    for (int mi = 0; mi < 4; mi++)
#pragma unroll
        for (int ni = 0; ni < 8; ni++)
#pragma unroll
            for (int r = 0; r < 4; r++) acc[mi][ni][r] = 0.f;

    for (int kt = 0; kt < NKT; ++kt) {
        cp_wait<STAGES - 2>();
        __syncthreads();
        const int buf = kt % STAGES;
        if (kt + STAGES - 1 < NKT) issue(kt + STAGES - 1, (kt + STAGES - 1) % STAGES);
        else cp_commit();

#pragma unroll
        for (int ks = 0; ks < 2; ++ks) {
            const int kb = ks * 8;
            unsigned a[4][4], b[8][2];
#pragma unroll
            for (int mi = 0; mi < 4; mi++) {
                int r = m0 + mi * 16 + g;
                a[mi][0] = f2tf(As[buf][r][kb + t]);
                a[mi][1] = f2tf(As[buf][r + 8][kb + t]);
                a[mi][2] = f2tf(As[buf][r][kb + 4 + t]);
                a[mi][3] = f2tf(As[buf][r + 8][kb + 4 + t]);
            }
#pragma unroll
            for (int ni = 0; ni < 8; ni++) {
                int cn = n0 + ni * 8 + g;
                b[ni][0] = f2tf(Bs[buf][kb + t][cn]);
                b[ni][1] = f2tf(Bs[buf][kb + 4 + t][cn]);
            }
#pragma unroll
            for (int mi = 0; mi < 4; mi++)
#pragma unroll
                for (int ni = 0; ni < 8; ni++)
                    mma_tf32(acc[mi][ni], a[mi][0], a[mi][1], a[mi][2], a[mi][3],
                             b[ni][0], b[ni][1]);
        }
        __syncthreads();
    }

    const int rbase = blockIdx.y * 128 + m0;
    const int cbase = blockIdx.x * 128 + n0;
#pragma unroll
    for (int mi = 0; mi < 4; mi++) {
#pragma unroll
        for (int ni = 0; ni < 8; ni++) {
            int r = rbase + mi * 16 + g;
            int c = cbase + ni * 8 + 2 * t;
            float2 bb = *(const float2*)&bias[c];
            float2 v0 = { acc[mi][ni][0] + bb.x, acc[mi][ni][1] + bb.y };
            float2 v1 = { acc[mi][ni][2] + bb.x, acc[mi][ni][3] + bb.y };
            *(float2*)&C[(size_t)r * Dm + c]       = v0;
            *(float2*)&C[(size_t)(r + 8) * Dm + c] = v1;
        }
    }
}

// =============================================================================
// Scores kernel (fp16 m16n8k16): E(fp16) = exp((Q@K^T)/8) + fp32 row partials.
// =============================================================================
__global__ void __launch_bounds__(256, 2) scores_tc_kernel(
    const __half* __restrict__ Q, const __half* __restrict__ K,
    __half* __restrict__ E, float* __restrict__ Zp)
{
    extern __shared__ __half hsm[];
    __half (*Qs)[72] = (__half(*)[72])hsm;
    __half (*Ks)[72] = (__half(*)[72])(hsm + 128 * 72);
    __shared__ float wsum[4][128];

    const int tid  = threadIdx.x;
    const int lane = tid & 31;
    const int wid  = tid >> 5;
    const int g = lane >> 2, t = lane & 3;
    const int m0 = (wid & 1) * 64;
    const int n0 = (wid >> 1) * 32;
    const int nwid = wid >> 1;

    const __half* Qb = Q + (size_t)blockIdx.z * Sq * Dk + (size_t)blockIdx.y * 128 * Dk;
    const __half* Kb = K + (size_t)blockIdx.z * Sq * Dk + (size_t)blockIdx.x * 128 * Dk;

#pragma unroll
    for (int i = 0; i < 4; ++i) {
        int idx = i * 256 + tid;
        int row = idx >> 3;
        int c8  = (idx & 7) * 8;
        *(uint4*)&Qs[row][c8] = *(const uint4*)&Qb[(size_t)row * Dk + c8];
        *(uint4*)&Ks[row][c8] = *(const uint4*)&Kb[(size_t)row * Dk + c8];
    }
    __syncthreads();

    float acc[4][4][4];
#pragma unroll
    for (int mi = 0; mi < 4; mi++)
#pragma unroll
        for (int ni = 0; ni < 4; ni++)
#pragma unroll
            for (int r = 0; r < 4; r++) acc[mi][ni][r] = 0.f;

#pragma unroll
    for (int ks = 0; ks < 4; ++ks) {
        const int kb = ks * 16;
        unsigned a[4][4], b[4][2];
#pragma unroll
        for (int mi = 0; mi < 4; mi++) {
            int r = m0 + mi * 16 + g;
            a[mi][0] = *(const unsigned*)&Qs[r][kb + 2 * t];
            a[mi][1] = *(const unsigned*)&Qs[r + 8][kb + 2 * t];
            a[mi][2] = *(const unsigned*)&Qs[r][kb + 2 * t + 8];
            a[mi][3] = *(const unsigned*)&Qs[r + 8][kb + 2 * t + 8];
        }
#pragma unroll
        for (int ni = 0; ni < 4; ni++) {
            int cn = n0 + ni * 8 + g;
            b[ni][0] = *(const unsigned*)&Ks[cn][kb + 2 * t];
            b[ni][1] = *(const unsigned*)&Ks[cn][kb + 2 * t + 8];
        }
#pragma unroll
        for (int mi = 0; mi < 4; mi++)
#pragma unroll
            for (int ni = 0; ni < 4; ni++)
                mma_f16(acc[mi][ni], a[mi][0], a[mi][1], a[mi][2], a[mi][3],
                        b[ni][0], b[ni][1]);
    }

    __half* Eb = E + (size_t)blockIdx.z * Sq * Sq;
    const int rbase = blockIdx.y * 128 + m0;
    const int cbase = blockIdx.x * 128 + n0;
#pragma unroll
    for (int mi = 0; mi < 4; mi++) {
        float s0 = 0.f, s1 = 0.f;
        int r = rbase + mi * 16 + g;
#pragma unroll
        for (int ni = 0; ni < 4; ni++) {
            int c = cbase + ni * 8 + 2 * t;
            float e00 = __expf(acc[mi][ni][0] * 0.125f);
            float e01 = __expf(acc[mi][ni][1] * 0.125f);
            float e10 = __expf(acc[mi][ni][2] * 0.125f);
            float e11 = __expf(acc[mi][ni][3] * 0.125f);
            __half2 h0 = __floats2half2_rn(e00, e01);
            __half2 h1 = __floats2half2_rn(e10, e11);
            stg_cs4((unsigned*)&Eb[(size_t)r * Sq + c],       *(unsigned*)&h0);
            stg_cs4((unsigned*)&Eb[(size_t)(r + 8) * Sq + c], *(unsigned*)&h1);
            s0 += e00 + e01;
            s1 += e10 + e11;
        }
        s0 += __shfl_xor_sync(0xffffffffu, s0, 1);
        s0 += __shfl_xor_sync(0xffffffffu, s0, 2);
        s1 += __shfl_xor_sync(0xffffffffu, s1, 1);
        s1 += __shfl_xor_sync(0xffffffffu, s1, 2);
        if (t == 0) {
            wsum[nwid][m0 + mi * 16 + g]     = s0;
            wsum[nwid][m0 + mi * 16 + g + 8] = s1;
        }
    }
    __syncthreads();
    if (tid < 128) {
        float zp = (wsum[0][tid] + wsum[1][tid]) + (wsum[2][tid] + wsum[3][tid]);
        Zp[(size_t)blockIdx.x * NROWS + (size_t)blockIdx.z * Sq
           + blockIdx.y * 128 + tid] = zp;
    }
}

// =============================================================================
// Z reduce: RZ[row] = 0.25 / sum_x Zp[x][row]
// =============================================================================
__global__ void __launch_bounds__(256) zred_kernel(
    const float* __restrict__ Zp, float* __restrict__ RZ)
{
    int i = blockIdx.x * 256 + threadIdx.x;
    float s = 0.f;
#pragma unroll
    for (int x = 0; x < NXT; x++) s += Zp[(size_t)x * NROWS + i];
    RZ[i] = 0.25f / s;
}

// =============================================================================
// Fused avg + avg@V (fp16 m16n8k16, BK=32, 3-stage V + 1 sync/iter):
// block 128(q) x 256(Dm). 256 thr, 8 warps (2m x 4n), warp 64x64.
// Register-prefetch fp16 E; V^T via 3-stage cp.async with cp_wait<1> at the
// TOP of the loop (V latency hidden across ~2 iterations); single
// __syncthreads per iteration (As double-buffered; warp skew bounded by the
// top sync, so no cross-buffer races — see R11 safety argument).
// smem: rzs f32[512] | As half[2][128][40] | Bs half[3][256][40]
// =============================================================================
#define AVB_RZ 0
#define AVB_AS 2048
#define AVB_BS (2048 + 2*128*40*2)
#define AVB_TOTAL (2048 + 2*128*40*2 + 3*256*40*2)   // 83968 B

__global__ void __launch_bounds__(256, 1) avgv_fused_kernel(
    const __half* __restrict__ E, const float* __restrict__ RZ,
    const __half* __restrict__ Vt, float* __restrict__ avg,
    float* __restrict__ Opre)
{
    extern __shared__ char avsm[];
    float* rzs = (float*)(avsm + AVB_RZ);                    // [row*4+h]
    __half (*As)[128][40] = (__half(*)[128][40])(avsm + AVB_AS);
    __half (*Bs)[256][40] = (__half(*)[256][40])(avsm + AVB_BS);

    const int tid  = threadIdx.x;
    const int lane = tid & 31;
    const int wid  = tid >> 5;
    const int g = lane >> 2, t = lane & 3;
    const int m0 = (wid & 1) * 64;
    const int n0 = (wid >> 1) * 64;

    const int b  = blockIdx.z;
    const int qb = blockIdx.y * 128;

    const __half* Ep[Hh];
#pragma unroll
    for (int h = 0; h < Hh; h++)
        Ep[h] = E + ((size_t)(b * Hh + h) * Sq + qb) * Sq;
    const __half* Vtb = Vt + (size_t)b * Dm * Sq;
    float* avgb = avg + ((size_t)b * Sq + qb) * Sq;

    // rz staging (128 rows x 4 heads)
    for (int i = tid; i < 512; i += 256) {
        int h = i & 3, row = i >> 2;
        rzs[row * 4 + h] = RZ[(size_t)(b * Hh + h) * Sq + qb + row];
    }

    const int erow = tid >> 1;            // 0..127
    const int esel = (tid & 1) * 16;      // 0 or 16 (halves within BK=32)

    uint4 pe[Hh][2];

    auto loadA = [&](int kt) {
#pragma unroll
        for (int h = 0; h < Hh; h++) {
            pe[h][0] = ldg_cs16(Ep[h] + (size_t)erow * Sq + kt * 32 + esel);
            pe[h][1] = ldg_cs16(Ep[h] + (size_t)erow * Sq + kt * 32 + esel + 8);
        }
    };
    // V^T tile: 256 n-rows x 32 k halves; each thread loads 64B of row tid
    auto issueB = [&](int kt, int st) {
#pragma unroll
        for (int j = 0; j < 4; j++)
            cp_async16(&Bs[st][tid][j * 8], Vtb + (size_t)tid * Sq + kt * 32 + j * 8);
        cp_commit();
    };
    auto storeA = [&](int buf, int kt) {
        float c[16];
#pragma unroll
        for (int j = 0; j < 16; j++) c[j] = 0.f;
#pragma unroll
        for (int h = 0; h < Hh; h++) {
            float rz = rzs[erow * 4 + h];
            const __half2* hp = (const __half2*)&pe[h][0];
#pragma unroll
            for (int j = 0; j < 8; j++) {
                float2 f = __half22float2(hp[j]);
                c[2*j]   += f.x * rz;
                c[2*j+1] += f.y * rz;
            }
        }
#pragma unroll
        for (int j = 0; j < 4; j++) {
            float4 cv = { c[4*j], c[4*j+1], c[4*j+2], c[4*j+3] };
            stg_cs16(&avgb[(size_t)erow * Sq + kt * 32 + esel + 4*j], cv);
        }
        __half2 hh[8];
#pragma unroll
        for (int j = 0; j < 8; j++) hh[j] = __floats2half2_rn(c[2*j], c[2*j+1]);
        *(uint4*)&As[buf][erow][esel]     = *(uint4*)&hh[0];
        *(uint4*)&As[buf][erow][esel + 8] = *(uint4*)&hh[4];
    };

    float acc[4][8][4];
#pragma unroll
    for (int mi = 0; mi < 4; mi++)
#pragma unroll
        for (int ni = 0; ni < 8; ni++)
#pragma unroll
            for (int r = 0; r < 4; r++) acc[mi][ni][r] = 0.f;

    const int NKT = Sq / 32;    // 64

    // prologue: pe=E(0); V stages 0 and 1 in flight; As[0] built
    loadA(0);
    issueB(0, 0);
    issueB(1, 1);
    __syncthreads();            // rzs visible
    storeA(0, 0);

    for (int kt = 0; kt < NKT; ++kt) {
        const int buf = kt & 1;
        const int vs  = kt % 3;

        cp_wait<1>();           // V stage kt complete (stage kt+1 may be in flight)
        __syncthreads();        // all As/Bs writes for this iter visible; skew <= 1 iter

        if (kt + 1 < NKT) loadA(kt + 1);
        if (kt + 2 < NKT) issueB(kt + 2, (kt + 2) % 3);
        else cp_commit();       // keep group sequence advancing for cp_wait<1>

#pragma unroll
        for (int ks = 0; ks < 2; ++ks) {
            const int kb = ks * 16;
            unsigned a[4][4], bb[8][2];
#pragma unroll
            for (int mi = 0; mi < 4; mi++) {
                int r = m0 + mi * 16 + g;
                a[mi][0] = *(const unsigned*)&As[buf][r][kb + 2 * t];
                a[mi][1] = *(const unsigned*)&As[buf][r + 8][kb + 2 * t];
                a[mi][2] = *(const unsigned*)&As[buf][r][kb + 2 * t + 8];
                a[mi][3] = *(const unsigned*)&As[buf][r + 8][kb + 2 * t + 8];
            }
#pragma unroll
            for (int ni = 0; ni < 8; ni++) {
                int cn = n0 + ni * 8 + g;
                bb[ni][0] = *(const unsigned*)&Bs[vs][cn][kb + 2 * t];
                bb[ni][1] = *(const unsigned*)&Bs[vs][cn][kb + 2 * t + 8];
            }
#pragma unroll
            for (int mi = 0; mi < 4; mi++)
#pragma unroll
                for (int ni = 0; ni < 8; ni++)
                    mma_f16(acc[mi][ni], a[mi][0], a[mi][1], a[mi][2], a[mi][3],
                            bb[ni][0], bb[ni][1]);
        }

        if (kt + 1 < NKT) storeA(buf ^ 1, kt + 1);
    }

    float* Ob = Opre + (size_t)b * Sq * Dm;
    const int rbase = qb + m0;
    const int cbase = n0;
#pragma unroll
    for (int mi = 0; mi < 4; mi++) {
#pragma unroll
        for (int ni = 0; ni < 8; ni++) {
            int r = rbase + mi * 16 + g;
            int c = cbase + ni * 8 + 2 * t;
            float2 v0 = { acc[mi][ni][0], acc[mi][ni][1] };
            float2 v1 = { acc[mi][ni][2], acc[mi][ni][3] };
            *(float2*)&Ob[(size_t)r * Dm + c]       = v0;
            *(float2*)&Ob[(size_t)(r + 8) * Dm + c] = v1;
        }
    }
}

// =============================================================================
// Launch
// =============================================================================
extern "C" void kernel_launch(void* const* d_in, const int* in_sizes, int n_in,
                              void* d_out, int out_size)
{
    (void)in_sizes; (void)n_in; (void)out_size;
    const float* query = (const float*)d_in[0];
    const float* key   = (const float*)d_in[1];
    const float* value = (const float*)d_in[2];
    const float* W_q   = (const float*)d_in[3];
    const float* b_q   = (const float*)d_in[4];
    const float* W_k   = (const float*)d_in[5];
    const float* b_k   = (const float*)d_in[6];
    const float* W_v   = (const float*)d_in[7];
    const float* b_v   = (const float*)d_in[8];
    const float* W_o   = (const float*)d_in[9];
    const float* b_o   = (const float*)d_in[10];

    float* out = (float*)d_out;                 // (B,S,D)
    float* avg = out + OUT0_ELEMS;              // (B,S,S)

    float *pO, *pZp, *pRZ;
    __half *pQ, *pK, *pVt, *pE;
    cudaGetSymbolAddress((void**)&pQ,  g_Q);
    cudaGetSymbolAddress((void**)&pK,  g_K);
    cudaGetSymbolAddress((void**)&pVt, g_Vt);
    cudaGetSymbolAddress((void**)&pE,  g_E);
    cudaGetSymbolAddress((void**)&pO,  g_O);
    cudaGetSymbolAddress((void**)&pZp, g_Zp);
    cudaGetSymbolAddress((void**)&pRZ, g_RZ);

    const int gemm_smem = (STAGES * 128 * 20 + STAGES * 16 * 136) * 4;
    cudaFuncSetAttribute(qkv_proj_kernel,
        cudaFuncAttributeMaxDynamicSharedMemorySize, gemm_smem);
    cudaFuncSetAttribute(oproj_kernel,
        cudaFuncAttributeMaxDynamicSharedMemorySize, gemm_smem);

    // 1: fused Q/K/V projections (fp16 outputs; V transposed)
    {
        dim3 grid(Dm / 128, NTOK / 128, 3);
        qkv_proj_kernel<<<grid, 128, gemm_smem>>>(
            query, key, value, W_q, W_k, W_v, b_q, b_k, b_v, pQ, pK, pVt);
    }

    // 2: E(fp16) = exp(Q@K^T / 8) + fp32 row-sum partials (fp16 MMA)
    {
        const int smem = 2 * 128 * 72 * 2;   // 36864 B
        cudaFuncSetAttribute(scores_tc_kernel,
            cudaFuncAttributeMaxDynamicSharedMemorySize, smem);
        dim3 grid(Sq / 128, Sq / 128, Bsz * Hh);
        scores_tc_kernel<<<grid, 256, smem>>>(pQ, pK, pE, pZp);
    }

    // 3: deterministic Z reduce -> 0.25/Z
    zred_kernel<<<NROWS / 256, 256>>>(pZp, pRZ);

    // 4: fused avg_attn production + avg@V (fp16 MMA, BK=32, 3-stage V)
    {
        cudaFuncSetAttribute(avgv_fused_kernel,
            cudaFuncAttributeMaxDynamicSharedMemorySize, AVB_TOTAL);
        dim3 grid(1, Sq / 128, Bsz);
        avgv_fused_kernel<<<grid, 256, AVB_TOTAL>>>(pE, pRZ, pVt, avg, pO);
    }

    // 5: final projection out = Opre @ W_o + b_o
    {
        dim3 grid(Dm / 128, NTOK / 128, 1);
        oproj_kernel<<<grid, 128, gemm_smem>>>(pO, W_o, out, b_o);
    }
}

// round 14
// speedup vs baseline: 1.1154x; 1.1154x over previous
#include <cuda_runtime.h>
#include <cuda_fp16.h>
#include <cstdint>
#include <math.h>

// Problem constants
#define Bsz 8
#define Sq  2048
#define Dm  256
#define Hh  4
#define Dk  64
#define NTOK (Bsz*Sq)          // 16384
#define OUT0_ELEMS ((size_t)NTOK*Dm) // 4194304
#define NROWS (Bsz*Hh*Sq)      // 65536 (b,h,q) rows
#define NXT 16                 // k-tiles per score row (2048/128)

// ---------------- scratch (static device globals; allocation-free contract) ---
__device__ __half g_Q[(size_t)Bsz*Hh*Sq*Dk];   // (b,h,q,d) fp16, 8MB
__device__ __half g_K[(size_t)Bsz*Hh*Sq*Dk];   // 8MB
__device__ __half g_Vt[(size_t)Bsz*Dm*Sq];     // V^T (b,d,tok) fp16, 8MB
__device__ __half g_E[(size_t)Bsz*Hh*Sq*Sq];   // exp(scores) fp16, 256MiB
__device__ float  g_O[(size_t)NTOK*Dm];        // attn output pre-proj, 16MB
__device__ float  g_Zp[(size_t)NXT*NROWS];     // per-k-tile row-sum partials (fp32)
__device__ float  g_RZ[(size_t)NROWS];         // 0.25 / rowsum

// =============================================================================
// helpers
// =============================================================================
__device__ __forceinline__ unsigned f2tf(float f) {
    unsigned u;
    asm("cvt.rna.tf32.f32 %0, %1;" : "=r"(u) : "f"(f));
    return u;
}
__device__ __forceinline__ void mma_tf32(float c[4],
    unsigned a0, unsigned a1, unsigned a2, unsigned a3,
    unsigned b0, unsigned b1)
{
    asm volatile(
        "mma.sync.aligned.m16n8k8.row.col.f32.tf32.tf32.f32 "
        "{%0,%1,%2,%3},{%4,%5,%6,%7},{%8,%9},{%0,%1,%2,%3};"
        : "+f"(c[0]), "+f"(c[1]), "+f"(c[2]), "+f"(c[3])
        : "r"(a0), "r"(a1), "r"(a2), "r"(a3), "r"(b0), "r"(b1));
}
__device__ __forceinline__ void mma_f16(float c[4],
    unsigned a0, unsigned a1, unsigned a2, unsigned a3,
    unsigned b0, unsigned b1)
{
    asm volatile(
        "mma.sync.aligned.m16n8k16.row.col.f32.f16.f16.f32 "
        "{%0,%1,%2,%3},{%4,%5,%6,%7},{%8,%9},{%0,%1,%2,%3};"
        : "+f"(c[0]), "+f"(c[1]), "+f"(c[2]), "+f"(c[3])
        : "r"(a0), "r"(a1), "r"(a2), "r"(a3), "r"(b0), "r"(b1));
}
__device__ __forceinline__ void cp_async16(void* smem, const void* gmem) {
    unsigned saddr = (unsigned)__cvta_generic_to_shared(smem);
    asm volatile("cp.async.cg.shared.global [%0], [%1], 16;\n"
                 :: "r"(saddr), "l"(gmem));
}
__device__ __forceinline__ void cp_commit() {
    asm volatile("cp.async.commit_group;\n");
}
template<int N>
__device__ __forceinline__ void cp_wait() {
    asm volatile("cp.async.wait_group %0;\n" :: "n"(N));
}
__device__ __forceinline__ void stg_cs16(float* p, float4 v) {
    asm volatile("st.global.cs.v4.f32 [%0], {%1,%2,%3,%4};"
                 :: "l"(p), "f"(v.x), "f"(v.y), "f"(v.z), "f"(v.w) : "memory");
}
__device__ __forceinline__ void stg_cs4(unsigned* p, unsigned v) {
    asm volatile("st.global.cs.b32 [%0], %1;" :: "l"(p), "r"(v) : "memory");
}
__device__ __forceinline__ uint4 ldg_cs16(const void* p) {
    uint4 v;
    asm volatile("ld.global.cs.v4.b32 {%0,%1,%2,%3}, [%4];"
                 : "=r"(v.x), "=r"(v.y), "=r"(v.z), "=r"(v.w) : "l"(p));
    return v;
}

#define STAGES 4

// =============================================================================
// Fused QKV projection (tf32 GEMM, fp16 outputs): grid.z selects operands.
// z=0/1: Q/K head-major fp16 scatter. z=2: V^T fp16 (b, d, tok).
// =============================================================================
__global__ void __launch_bounds__(128, 2) qkv_proj_kernel(
    const float* __restrict__ q, const float* __restrict__ k, const float* __restrict__ v,
    const float* __restrict__ Wq, const float* __restrict__ Wk, const float* __restrict__ Wv,
    const float* __restrict__ bq, const float* __restrict__ bk, const float* __restrict__ bv,
    __half* __restrict__ Cq, __half* __restrict__ Ck, __half* __restrict__ Vt)
{
    extern __shared__ float dsm[];
    float (*As)[128][20]  = (float(*)[128][20])dsm;
    float (*Bs)[16][136]  = (float(*)[16][136])(dsm + STAGES * 128 * 20);

    const int sel = blockIdx.z;
    const float* A    = sel == 0 ? q  : sel == 1 ? k  : v;
    const float* B    = sel == 0 ? Wq : sel == 1 ? Wk : Wv;
    const float* bias = sel == 0 ? bq : sel == 1 ? bk : bv;

    const int tid  = threadIdx.x;
    const int lane = tid & 31;
    const int wid  = tid >> 5;
    const int g = lane >> 2, t = lane & 3;
    const int m0 = (wid & 1) * 64;
    const int n0 = (wid >> 1) * 64;

    const float* Ab = A + (size_t)blockIdx.y * 128 * Dm;
    const float* Bb = B + blockIdx.x * 128;

    const int arow = tid >> 2;
    const int acol = (tid & 3) * 4;
    const int brow = tid >> 5;
    const int bcol = (tid & 31) * 4;

    const int NKT = Dm / 16;   // 16

    auto issue = [&](int kt, int st) {
#pragma unroll
        for (int i = 0; i < 4; i++)
            cp_async16(&As[st][arow + 32 * i][acol],
                       Ab + (size_t)(arow + 32 * i) * Dm + kt * 16 + acol);
#pragma unroll
        for (int i = 0; i < 4; i++)
            cp_async16(&Bs[st][brow + 4 * i][bcol],
                       Bb + (size_t)(kt * 16 + brow + 4 * i) * Dm + bcol);
        cp_commit();
    };

#pragma unroll
    for (int s = 0; s < STAGES - 1; ++s) issue(s, s);

    float acc[4][8][4];
#pragma unroll
    for (int mi = 0; mi < 4; mi++)
#pragma unroll
        for (int ni = 0; ni < 8; ni++)
#pragma unroll
            for (int r = 0; r < 4; r++) acc[mi][ni][r] = 0.f;

    for (int kt = 0; kt < NKT; ++kt) {
        cp_wait<STAGES - 2>();
        __syncthreads();
        const int buf = kt % STAGES;
        if (kt + STAGES - 1 < NKT) issue(kt + STAGES - 1, (kt + STAGES - 1) % STAGES);
        else cp_commit();

#pragma unroll
        for (int ks = 0; ks < 2; ++ks) {
            const int kb = ks * 8;
            unsigned a[4][4], b[8][2];
#pragma unroll
            for (int mi = 0; mi < 4; mi++) {
                int r = m0 + mi * 16 + g;
                a[mi][0] = f2tf(As[buf][r][kb + t]);
                a[mi][1] = f2tf(As[buf][r + 8][kb + t]);
                a[mi][2] = f2tf(As[buf][r][kb + 4 + t]);
                a[mi][3] = f2tf(As[buf][r + 8][kb + 4 + t]);
            }
#pragma unroll
            for (int ni = 0; ni < 8; ni++) {
                int cn = n0 + ni * 8 + g;
                b[ni][0] = f2tf(Bs[buf][kb + t][cn]);
                b[ni][1] = f2tf(Bs[buf][kb + 4 + t][cn]);
            }
#pragma unroll
            for (int mi = 0; mi < 4; mi++)
#pragma unroll
                for (int ni = 0; ni < 8; ni++)
                    mma_tf32(acc[mi][ni], a[mi][0], a[mi][1], a[mi][2], a[mi][3],
                             b[ni][0], b[ni][1]);
        }
        __syncthreads();
    }

    const int rbase = blockIdx.y * 128 + m0;
    const int cbase = blockIdx.x * 128 + n0;
#pragma unroll
    for (int mi = 0; mi < 4; mi++) {
#pragma unroll
        for (int ni = 0; ni < 8; ni++) {
            int r = rbase + mi * 16 + g;
            int c = cbase + ni * 8 + 2 * t;
            float2 bb = *(const float2*)&bias[c];
            float2 v0 = { acc[mi][ni][0] + bb.x, acc[mi][ni][1] + bb.y };
            float2 v1 = { acc[mi][ni][2] + bb.x, acc[mi][ni][3] + bb.y };
            if (sel < 2) {
                __half* C = sel == 0 ? Cq : Ck;
                int b0i = r >> 11, q0 = r & 2047;
                int h = c >> 6, d = c & 63;
                __half2 h0 = __floats2half2_rn(v0.x, v0.y);
                __half2 h1 = __floats2half2_rn(v1.x, v1.y);
                *(__half2*)&C[((size_t)((b0i * Hh + h) * Sq) + q0) * Dk + d] = h0;
                int r1 = r + 8;
                int b1i = r1 >> 11, q1 = r1 & 2047;
                *(__half2*)&C[((size_t)((b1i * Hh + h) * Sq) + q1) * Dk + d] = h1;
            } else {
                int b0i = r >> 11, tok0 = r & 2047;
                Vt[((size_t)(b0i * Dm + c)     * Sq) + tok0] = __float2half_rn(v0.x);
                Vt[((size_t)(b0i * Dm + c + 1) * Sq) + tok0] = __float2half_rn(v0.y);
                int r1 = r + 8;
                int b1i = r1 >> 11, tok1 = r1 & 2047;
                Vt[((size_t)(b1i * Dm + c)     * Sq) + tok1] = __float2half_rn(v1.x);
                Vt[((size_t)(b1i * Dm + c + 1) * Sq) + tok1] = __float2half_rn(v1.y);
            }
        }
    }
}

// =============================================================================
// Final projection: out = Opre @ W_o + b_o (tf32, fp32 in/out)
// =============================================================================
__global__ void __launch_bounds__(128, 2) oproj_kernel(
    const float* __restrict__ A, const float* __restrict__ B,
    float* __restrict__ C, const float* __restrict__ bias)
{
    extern __shared__ float dsm[];
    float (*As)[128][20]  = (float(*)[128][20])dsm;
    float (*Bs)[16][136]  = (float(*)[16][136])(dsm + STAGES * 128 * 20);

    const int tid  = threadIdx.x;
    const int lane = tid & 31;
    const int wid  = tid >> 5;
    const int g = lane >> 2, t = lane & 3;
    const int m0 = (wid & 1) * 64;
    const int n0 = (wid >> 1) * 64;

    const float* Ab = A + (size_t)blockIdx.y * 128 * Dm;
    const float* Bb = B + blockIdx.x * 128;

    const int arow = tid >> 2;
    const int acol = (tid & 3) * 4;
    const int brow = tid >> 5;
    const int bcol = (tid & 31) * 4;

    const int NKT = Dm / 16;

    auto issue = [&](int kt, int st) {
#pragma unroll
        for (int i = 0; i < 4; i++)
            cp_async16(&As[st][arow + 32 * i][acol],
                       Ab + (size_t)(arow + 32 * i) * Dm + kt * 16 + acol);
#pragma unroll
        for (int i = 0; i < 4; i++)
            cp_async16(&Bs[st][brow + 4 * i][bcol],
                       Bb + (size_t)(kt * 16 + brow + 4 * i) * Dm + bcol);
        cp_commit();
    };

#pragma unroll
    for (int s = 0; s < STAGES - 1; ++s) issue(s, s);

    float acc[4][8][4];
#pragma unroll
    for (int mi = 0; mi < 4; mi++)
#pragma unroll
        for (int ni = 0; ni < 8; ni++)
#pragma unroll
            for (int r = 0; r < 4; r++) acc[mi][ni][r] = 0.f;

    for (int kt = 0; kt < NKT; ++kt) {
        cp_wait<STAGES - 2>();
        __syncthreads();
        const int buf = kt % STAGES;
        if (kt + STAGES - 1 < NKT) issue(kt + STAGES - 1, (kt + STAGES - 1) % STAGES);
        else cp_commit();

#pragma unroll
        for (int ks = 0; ks < 2; ++ks) {
            const int kb = ks * 8;
            unsigned a[4][4], b[8][2];
#pragma unroll
            for (int mi = 0; mi < 4; mi++) {
                int r = m0 + mi * 16 + g;
                a[mi][0] = f2tf(As[buf][r][kb + t]);
                a[mi][1] = f2tf(As[buf][r + 8][kb + t]);
                a[mi][2] = f2tf(As[buf][r][kb + 4 + t]);
                a[mi][3] = f2tf(As[buf][r + 8][kb + 4 + t]);
            }
#pragma unroll
            for (int ni = 0; ni < 8; ni++) {
                int cn = n0 + ni * 8 + g;
                b[ni][0] = f2tf(Bs[buf][kb + t][cn]);
                b[ni][1] = f2tf(Bs[buf][kb + 4 + t][cn]);
            }
#pragma unroll
            for (int mi = 0; mi < 4; mi++)
#pragma unroll
                for (int ni = 0; ni < 8; ni++)
                    mma_tf32(acc[mi][ni], a[mi][0], a[mi][1], a[mi][2], a[mi][3],
                             b[ni][0], b[ni][1]);
        }
        __syncthreads();
    }

    const int rbase = blockIdx.y * 128 + m0;
    const int cbase = blockIdx.x * 128 + n0;
#pragma unroll
    for (int mi = 0; mi < 4; mi++) {
#pragma unroll
        for (int ni = 0; ni < 8; ni++) {
            int r = rbase + mi * 16 + g;
            int c = cbase + ni * 8 + 2 * t;
            float2 bb = *(const float2*)&bias[c];
            float2 v0 = { acc[mi][ni][0] + bb.x, acc[mi][ni][1] + bb.y };
            float2 v1 = { acc[mi][ni][2] + bb.x, acc[mi][ni][3] + bb.y };
            *(float2*)&C[(size_t)r * Dm + c]       = v0;
            *(float2*)&C[(size_t)(r + 8) * Dm + c] = v1;
        }
    }
}

// =============================================================================
// Scores kernel (fp16 m16n8k16): E(fp16) = exp((Q@K^T)/8) + fp32 row partials.
// (unchanged from R10)
// =============================================================================
__global__ void __launch_bounds__(256, 2) scores_tc_kernel(
    const __half* __restrict__ Q, const __half* __restrict__ K,
    __half* __restrict__ E, float* __restrict__ Zp)
{
    extern __shared__ __half hsm[];
    __half (*Qs)[72] = (__half(*)[72])hsm;
    __half (*Ks)[72] = (__half(*)[72])(hsm + 128 * 72);
    __shared__ float wsum[4][128];

    const int tid  = threadIdx.x;
    const int lane = tid & 31;
    const int wid  = tid >> 5;
    const int g = lane >> 2, t = lane & 3;
    const int m0 = (wid & 1) * 64;
    const int n0 = (wid >> 1) * 32;
    const int nwid = wid >> 1;

    const __half* Qb = Q + (size_t)blockIdx.z * Sq * Dk + (size_t)blockIdx.y * 128 * Dk;
    const __half* Kb = K + (size_t)blockIdx.z * Sq * Dk + (size_t)blockIdx.x * 128 * Dk;

#pragma unroll
    for (int i = 0; i < 4; ++i) {
        int idx = i * 256 + tid;
        int row = idx >> 3;
        int c8  = (idx & 7) * 8;
        *(uint4*)&Qs[row][c8] = *(const uint4*)&Qb[(size_t)row * Dk + c8];
        *(uint4*)&Ks[row][c8] = *(const uint4*)&Kb[(size_t)row * Dk + c8];
    }
    __syncthreads();

    float acc[4][4][4];
#pragma unroll
    for (int mi = 0; mi < 4; mi++)
#pragma unroll
        for (int ni = 0; ni < 4; ni++)
#pragma unroll
            for (int r = 0; r < 4; r++) acc[mi][ni][r] = 0.f;

#pragma unroll
    for (int ks = 0; ks < 4; ++ks) {
        const int kb = ks * 16;
        unsigned a[4][4], b[4][2];
#pragma unroll
        for (int mi = 0; mi < 4; mi++) {
            int r = m0 + mi * 16 + g;
            a[mi][0] = *(const unsigned*)&Qs[r][kb + 2 * t];
            a[mi][1] = *(const unsigned*)&Qs[r + 8][kb + 2 * t];
            a[mi][2] = *(const unsigned*)&Qs[r][kb + 2 * t + 8];
            a[mi][3] = *(const unsigned*)&Qs[r + 8][kb + 2 * t + 8];
        }
#pragma unroll
        for (int ni = 0; ni < 4; ni++) {
            int cn = n0 + ni * 8 + g;
            b[ni][0] = *(const unsigned*)&Ks[cn][kb + 2 * t];
            b[ni][1] = *(const unsigned*)&Ks[cn][kb + 2 * t + 8];
        }
#pragma unroll
        for (int mi = 0; mi < 4; mi++)
#pragma unroll
            for (int ni = 0; ni < 4; ni++)
                mma_f16(acc[mi][ni], a[mi][0], a[mi][1], a[mi][2], a[mi][3],
                        b[ni][0], b[ni][1]);
    }

    __half* Eb = E + (size_t)blockIdx.z * Sq * Sq;
    const int rbase = blockIdx.y * 128 + m0;
    const int cbase = blockIdx.x * 128 + n0;
#pragma unroll
    for (int mi = 0; mi < 4; mi++) {
        float s0 = 0.f, s1 = 0.f;
        int r = rbase + mi * 16 + g;
#pragma unroll
        for (int ni = 0; ni < 4; ni++) {
            int c = cbase + ni * 8 + 2 * t;
            float e00 = __expf(acc[mi][ni][0] * 0.125f);
            float e01 = __expf(acc[mi][ni][1] * 0.125f);
            float e10 = __expf(acc[mi][ni][2] * 0.125f);
            float e11 = __expf(acc[mi][ni][3] * 0.125f);
            __half2 h0 = __floats2half2_rn(e00, e01);
            __half2 h1 = __floats2half2_rn(e10, e11);
            stg_cs4((unsigned*)&Eb[(size_t)r * Sq + c],       *(unsigned*)&h0);
            stg_cs4((unsigned*)&Eb[(size_t)(r + 8) * Sq + c], *(unsigned*)&h1);
            s0 += e00 + e01;
            s1 += e10 + e11;
        }
        s0 += __shfl_xor_sync(0xffffffffu, s0, 1);
        s0 += __shfl_xor_sync(0xffffffffu, s0, 2);
        s1 += __shfl_xor_sync(0xffffffffu, s1, 1);
        s1 += __shfl_xor_sync(0xffffffffu, s1, 2);
        if (t == 0) {
            wsum[nwid][m0 + mi * 16 + g]     = s0;
            wsum[nwid][m0 + mi * 16 + g + 8] = s1;
        }
    }
    __syncthreads();
    if (tid < 128) {
        float zp = (wsum[0][tid] + wsum[1][tid]) + (wsum[2][tid] + wsum[3][tid]);
        Zp[(size_t)blockIdx.x * NROWS + (size_t)blockIdx.z * Sq
           + blockIdx.y * 128 + tid] = zp;
    }
}

// =============================================================================
// Z reduce: RZ[row] = 0.25 / sum_x Zp[x][row]
// =============================================================================
__global__ void __launch_bounds__(256) zred_kernel(
    const float* __restrict__ Zp, float* __restrict__ RZ)
{
    int i = blockIdx.x * 256 + threadIdx.x;
    float s = 0.f;
#pragma unroll
    for (int x = 0; x < NXT; x++) s += Zp[(size_t)x * NROWS + i];
    RZ[i] = 0.25f / s;
}

// =============================================================================
// Fused avg + avg@V (fp16 m16n8k16, BK=32, 512 threads / 16 warps):
// block tile 128(q) x 256(Dm). Warp grid 4m x 4n, warp tile 32x64,
// acc 64 regs/thread, E prefetch 16 regs/thread -> 2x in-flight bytes vs R10.
// smem: rzs f32[512] | As half[2][128][40] | Bs half[2][256][40]
// =============================================================================
#define AVB_RZ 0
#define AVB_AS 2048
#define AVB_BS (2048 + 2*128*40*2)
#define AVB_TOTAL (2048 + 2*128*40*2 + 2*256*40*2)   // 63488 B

__global__ void __launch_bounds__(512, 1) avgv_fused_kernel(
    const __half* __restrict__ E, const float* __restrict__ RZ,
    const __half* __restrict__ Vt, float* __restrict__ avg,
    float* __restrict__ Opre)
{
    extern __shared__ char avsm[];
    float* rzs = (float*)(avsm + AVB_RZ);                    // [row*4+h]
    __half (*As)[128][40] = (__half(*)[128][40])(avsm + AVB_AS);
    __half (*Bs)[256][40] = (__half(*)[256][40])(avsm + AVB_BS);

    const int tid  = threadIdx.x;
    const int lane = tid & 31;
    const int wid  = tid >> 5;          // 0..15
    const int g = lane >> 2, t = lane & 3;
    const int m0 = (wid & 3) * 32;      // 4 m-tiles
    const int n0 = (wid >> 2) * 64;     // 4 n-tiles

    const int b  = blockIdx.z;
    const int qb = blockIdx.y * 128;

    const __half* Ep[Hh];
#pragma unroll
    for (int h = 0; h < Hh; h++)
        Ep[h] = E + ((size_t)(b * Hh + h) * Sq + qb) * Sq;
    const __half* Vtb = Vt + (size_t)b * Dm * Sq;
    float* avgb = avg + ((size_t)b * Sq + qb) * Sq;

    // rz staging (128 rows x 4 heads = 512 entries, one per thread)
    {
        int h = tid & 3, row = tid >> 2;
        rzs[row * 4 + h] = RZ[(size_t)(b * Hh + h) * Sq + qb + row];
    }

    const int erow = tid >> 2;            // 0..127
    const int eseg = (tid & 3) * 8;       // halves offset within BK=32: 0,8,16,24

    uint4 pe[Hh];

    auto loadA = [&](int kt) {
#pragma unroll
        for (int h = 0; h < Hh; h++)
            pe[h] = ldg_cs16(Ep[h] + (size_t)erow * Sq + kt * 32 + eseg);
    };
    // V^T tile: 256 n-rows x 32 k halves (64B/row); thread covers 32B:
    // row = tid>>1, col halves = (tid&1)*16
    auto issueB = [&](int kt, int buf) {
        int vrow = tid >> 1;
        int vcol = (tid & 1) * 16;
        cp_async16(&Bs[buf][vrow][vcol],     Vtb + (size_t)vrow * Sq + kt * 32 + vcol);
        cp_async16(&Bs[buf][vrow][vcol + 8], Vtb + (size_t)vrow * Sq + kt * 32 + vcol + 8);
        cp_commit();
    };
    auto storeA = [&](int buf, int kt) {
        float c[8];
#pragma unroll
        for (int j = 0; j < 8; j++) c[j] = 0.f;
#pragma unroll
        for (int h = 0; h < Hh; h++) {
            float rz = rzs[erow * 4 + h];
            const __half2* hp = (const __half2*)&pe[h];
#pragma unroll
            for (int j = 0; j < 4; j++) {
                float2 f = __half22float2(hp[j]);
                c[2*j]   += f.x * rz;
                c[2*j+1] += f.y * rz;
            }
        }
        float* arow = &avgb[(size_t)erow * Sq + kt * 32 + eseg];
        float4 c0 = { c[0], c[1], c[2], c[3] };
        float4 c1 = { c[4], c[5], c[6], c[7] };
        stg_cs16(arow,     c0);
        stg_cs16(arow + 4, c1);
        __half2 hh[4];
#pragma unroll
        for (int j = 0; j < 4; j++) hh[j] = __floats2half2_rn(c[2*j], c[2*j+1]);
        *(uint4*)&As[buf][erow][eseg] = *(uint4*)hh;
    };

    float acc[2][8][4];
#pragma unroll
    for (int mi = 0; mi < 2; mi++)
#pragma unroll
        for (int ni = 0; ni < 8; ni++)
#pragma unroll
            for (int r = 0; r < 4; r++) acc[mi][ni][r] = 0.f;

    loadA(0);
    issueB(0, 0);
    __syncthreads();            // rzs visible
    storeA(0, 0);
    cp_wait<0>();
    __syncthreads();

    const int NKT = Sq / 32;    // 64
    for (int kt = 0; kt < NKT; ++kt) {
        const int buf = kt & 1;
        if (kt + 1 < NKT) {
            loadA(kt + 1);
            issueB(kt + 1, buf ^ 1);
        }

#pragma unroll
        for (int ks = 0; ks < 2; ++ks) {
            const int kb = ks * 16;
            unsigned a[2][4], bb[8][2];
#pragma unroll
            for (int mi = 0; mi < 2; mi++) {
                int r = m0 + mi * 16 + g;
                a[mi][0] = *(const unsigned*)&As[buf][r][kb + 2 * t];
                a[mi][1] = *(const unsigned*)&As[buf][r + 8][kb + 2 * t];
                a[mi][2] = *(const unsigned*)&As[buf][r][kb + 2 * t + 8];
                a[mi][3] = *(const unsigned*)&As[buf][r + 8][kb + 2 * t + 8];
            }
#pragma unroll
            for (int ni = 0; ni < 8; ni++) {
                int cn = n0 + ni * 8 + g;
                bb[ni][0] = *(const unsigned*)&Bs[buf][cn][kb + 2 * t];
                bb[ni][1] = *(const unsigned*)&Bs[buf][cn][kb + 2 * t + 8];
            }
#pragma unroll
            for (int mi = 0; mi < 2; mi++)
#pragma unroll
                for (int ni = 0; ni < 8; ni++)
                    mma_f16(acc[mi][ni], a[mi][0], a[mi][1], a[mi][2], a[mi][3],
                            bb[ni][0], bb[ni][1]);
        }

        if (kt + 1 < NKT) {
            storeA(buf ^ 1, kt + 1);
            cp_wait<0>();
        }
        __syncthreads();
    }

    float* Ob = Opre + (size_t)b * Sq * Dm;
    const int rbase = qb + m0;
    const int cbase = n0;
#pragma unroll
    for (int mi = 0; mi < 2; mi++) {
#pragma unroll
        for (int ni = 0; ni < 8; ni++) {
            int r = rbase + mi * 16 + g;
            int c = cbase + ni * 8 + 2 * t;
            float2 v0 = { acc[mi][ni][0], acc[mi][ni][1] };
            float2 v1 = { acc[mi][ni][2], acc[mi][ni][3] };
            *(float2*)&Ob[(size_t)r * Dm + c]       = v0;
            *(float2*)&Ob[(size_t)(r + 8) * Dm + c] = v1;
        }
    }
}

// =============================================================================
// Launch
// =============================================================================
extern "C" void kernel_launch(void* const* d_in, const int* in_sizes, int n_in,
                              void* d_out, int out_size)
{
    (void)in_sizes; (void)n_in; (void)out_size;
    const float* query = (const float*)d_in[0];
    const float* key   = (const float*)d_in[1];
    const float* value = (const float*)d_in[2];
    const float* W_q   = (const float*)d_in[3];
    const float* b_q   = (const float*)d_in[4];
    const float* W_k   = (const float*)d_in[5];
    const float* b_k   = (const float*)d_in[6];
    const float* W_v   = (const float*)d_in[7];
    const float* b_v   = (const float*)d_in[8];
    const float* W_o   = (const float*)d_in[9];
    const float* b_o   = (const float*)d_in[10];

    float* out = (float*)d_out;                 // (B,S,D)
    float* avg = out + OUT0_ELEMS;              // (B,S,S)

    float *pO, *pZp, *pRZ;
    __half *pQ, *pK, *pVt, *pE;
    cudaGetSymbolAddress((void**)&pQ,  g_Q);
    cudaGetSymbolAddress((void**)&pK,  g_K);
    cudaGetSymbolAddress((void**)&pVt, g_Vt);
    cudaGetSymbolAddress((void**)&pE,  g_E);
    cudaGetSymbolAddress((void**)&pO,  g_O);
    cudaGetSymbolAddress((void**)&pZp, g_Zp);
    cudaGetSymbolAddress((void**)&pRZ, g_RZ);

    const int gemm_smem = (STAGES * 128 * 20 + STAGES * 16 * 136) * 4;
    cudaFuncSetAttribute(qkv_proj_kernel,
        cudaFuncAttributeMaxDynamicSharedMemorySize, gemm_smem);
    cudaFuncSetAttribute(oproj_kernel,
        cudaFuncAttributeMaxDynamicSharedMemorySize, gemm_smem);

    // 1: fused Q/K/V projections (fp16 outputs; V transposed)
    {
        dim3 grid(Dm / 128, NTOK / 128, 3);
        qkv_proj_kernel<<<grid, 128, gemm_smem>>>(
            query, key, value, W_q, W_k, W_v, b_q, b_k, b_v, pQ, pK, pVt);
    }

    // 2: E(fp16) = exp(Q@K^T / 8) + fp32 row-sum partials (fp16 MMA)
    {
        const int smem = 2 * 128 * 72 * 2;   // 36864 B
        cudaFuncSetAttribute(scores_tc_kernel,
            cudaFuncAttributeMaxDynamicSharedMemorySize, smem);
        dim3 grid(Sq / 128, Sq / 128, Bsz * Hh);
        scores_tc_kernel<<<grid, 256, smem>>>(pQ, pK, pE, pZp);
    }

    // 3: deterministic Z reduce -> 0.25/Z
    zred_kernel<<<NROWS / 256, 256>>>(pZp, pRZ);

    // 4: fused avg_attn production + avg@V (fp16 MMA, BK=32, 512 threads)
    {
        cudaFuncSetAttribute(avgv_fused_kernel,
            cudaFuncAttributeMaxDynamicSharedMemorySize, AVB_TOTAL);
        dim3 grid(1, Sq / 128, Bsz);
        avgv_fused_kernel<<<grid, 512, AVB_TOTAL>>>(pE, pRZ, pVt, avg, pO);
    }

    // 5: final projection out = Opre @ W_o + b_o
    {
        dim3 grid(Dm / 128, NTOK / 128, 1);
        oproj_kernel<<<grid, 128, gemm_smem>>>(pO, W_o, out, b_o);
    }
}